// round 15
// baseline (speedup 1.0000x reference)
#include <cuda_runtime.h>
#include <math.h>
#include <stdint.h>

#define NBATCH   8
#define NSAMPLES 2048
#define DIMX     4
#define NHID     64
#define NLAYERS  3
#define NN       (NBATCH * NSAMPLES)     // 16384 nodes
#define EE       (NN * 16)               // 262144 edges
#define EPSI     1e-5f

// ---------------- static device scratch ----------------
__device__ float g_h[NN * NHID];
__device__ float g_agg[NN * NHID];
__device__ __align__(16) float g_PQ[NN * 128];   // [P|Q] per node (P includes b1)
__device__ __align__(16) float g_X[NN * DIMX];
__device__ int   g_src[EE];
__device__ int   g_tgt[EE];
__device__ float g_t2[NBATCH];
__device__ float g_t3[NBATCH];
__device__ float g_sum[NBATCH * NHID];
__device__ float g_sqs[NBATCH * NHID];

// ---------------- tf32 helpers ----------------
// hi = round-to-nearest tf32; lo = raw fp32 residual bits (HW truncates low mantissa)
__device__ __forceinline__ void split_tf32(float x, uint32_t& hi, uint32_t& lo) {
    uint32_t h;
    asm("cvt.rna.tf32.f32 %0, %1;" : "=r"(h) : "f"(x));
    lo = __float_as_uint(x - __uint_as_float(h));
    hi = h;
}

__device__ __forceinline__ void mma_tf32(float c[4], const uint32_t a[4], const uint32_t b[2]) {
    asm volatile(
        "mma.sync.aligned.m16n8k8.row.col.f32.tf32.tf32.f32 "
        "{%0,%1,%2,%3}, {%4,%5,%6,%7}, {%8,%9}, {%0,%1,%2,%3};"
        : "+f"(c[0]), "+f"(c[1]), "+f"(c[2]), "+f"(c[3])
        : "r"(a[0]), "r"(a[1]), "r"(a[2]), "r"(a[3]), "r"(b[0]), "r"(b[1]));
}

__device__ __forceinline__ void red_add_v4(float* p, float4 v) {
    asm volatile("red.global.add.v4.f32 [%0], {%1,%2,%3,%4};"
                 :: "l"(p), "f"(v.x), "f"(v.y), "f"(v.z), "f"(v.w) : "memory");
}

__device__ __forceinline__ void red_add_v2(float* p, float a, float b) {
    asm volatile("red.global.add.v2.f32 [%0], {%1,%2};"
                 :: "l"(p), "f"(a), "f"(b) : "memory");
}

// ---------------- interleaved B staging ----------------
// w: [K][64] row-major. dst: [64 n][LDB floats], one float4 slot per (kg, tig):
// {h(k0+tig), h(k0+tig+4), l(k0+tig), l(k0+tig+4)} at n*LDB + kg*16 + tig*4.
// Scalar element: pos = n*LDB + (k>>3)*16 + (k&3)*4 + ((k>>2)&1); +2 for lo.
template<int K, int LDB>
__device__ __forceinline__ void stage_Bi(float* dst, const float* __restrict__ w) {
    int tid = threadIdx.x;
    for (int i = tid; i < K * 64; i += 256) {
        int k = i >> 6, n = i & 63;
        uint32_t h, l; split_tf32(w[i], h, l);
        int pos = n * LDB + ((k >> 3) << 4) + ((k & 3) << 2) + ((k >> 2) & 1);
        dst[pos]     = __uint_as_float(h);
        dst[pos + 2] = __uint_as_float(l);
    }
}

// ---------------- GEMM: A fp32 (split in loop), B interleaved float4 ----------------
template<int K, int LDA, int NT, int LDB>
__device__ __forceinline__ void gemm_sp2(const float* __restrict__ sA,
                                         const float* __restrict__ sB,
                                         int mr, int n0, int lane, float acc[2][NT][4]) {
    int gid = lane >> 2, tig = lane & 3;
    #pragma unroll
    for (int kg = 0; kg < K / 8; kg++) {
        int k0 = kg * 8;
        uint32_t ah[2][4], al[2][4];
        #pragma unroll
        for (int f = 0; f < 2; f++) {
            int r0 = mr + f * 16 + gid;
            split_tf32(sA[r0 * LDA + k0 + tig],           ah[f][0], al[f][0]);
            split_tf32(sA[(r0 + 8) * LDA + k0 + tig],     ah[f][1], al[f][1]);
            split_tf32(sA[r0 * LDA + k0 + tig + 4],       ah[f][2], al[f][2]);
            split_tf32(sA[(r0 + 8) * LDA + k0 + tig + 4], ah[f][3], al[f][3]);
        }
        #pragma unroll
        for (int nt = 0; nt < NT; nt++) {
            int c0 = n0 + nt * 8 + gid;
            float4 wv = *(const float4*)&sB[c0 * LDB + kg * 16 + tig * 4];
            uint32_t bh[2] = { __float_as_uint(wv.x), __float_as_uint(wv.y) };
            uint32_t bl[2] = { __float_as_uint(wv.z), __float_as_uint(wv.w) };
            #pragma unroll
            for (int f = 0; f < 2; f++) {
                mma_tf32(acc[f][nt], al[f], bh);
                mma_tf32(acc[f][nt], ah[f], bl);
                mma_tf32(acc[f][nt], ah[f], bh);
            }
        }
    }
}

// ---------------- GEMM: A interleaved float4, B interleaved float4 ----------------
template<int K, int LDA, int NT, int LDB>
__device__ __forceinline__ void gemm_ii(const float* __restrict__ sA,
                                        const float* __restrict__ sB,
                                        int mr, int n0, int lane, float acc[2][NT][4]) {
    int gid = lane >> 2, tig = lane & 3;
    #pragma unroll
    for (int kg = 0; kg < K / 8; kg++) {
        uint32_t ah[2][4], al[2][4];
        #pragma unroll
        for (int f = 0; f < 2; f++) {
            int r0 = mr + f * 16 + gid;
            float4 v0 = *(const float4*)&sA[r0 * LDA + kg * 16 + tig * 4];
            float4 v1 = *(const float4*)&sA[(r0 + 8) * LDA + kg * 16 + tig * 4];
            ah[f][0] = __float_as_uint(v0.x); ah[f][1] = __float_as_uint(v1.x);
            ah[f][2] = __float_as_uint(v0.y); ah[f][3] = __float_as_uint(v1.y);
            al[f][0] = __float_as_uint(v0.z); al[f][1] = __float_as_uint(v1.z);
            al[f][2] = __float_as_uint(v0.w); al[f][3] = __float_as_uint(v1.w);
        }
        #pragma unroll
        for (int nt = 0; nt < NT; nt++) {
            int c0 = n0 + nt * 8 + gid;
            float4 wv = *(const float4*)&sB[c0 * LDB + kg * 16 + tig * 4];
            uint32_t bh[2] = { __float_as_uint(wv.x), __float_as_uint(wv.y) };
            uint32_t bl[2] = { __float_as_uint(wv.z), __float_as_uint(wv.w) };
            #pragma unroll
            for (int f = 0; f < 2; f++) {
                mma_tf32(acc[f][nt], al[f], bh);
                mma_tf32(acc[f][nt], ah[f], bl);
                mma_tf32(acc[f][nt], ah[f], bh);
            }
        }
    }
}

// ---------------- edge index decode (+ t2/t3 zeroing) ----------------
__global__ void cvt_edges_kernel(const int* __restrict__ raw) {
    __shared__ int is64;
    if (blockIdx.x == 0 && threadIdx.x < NBATCH) {
        g_t2[threadIdx.x] = 0.f; g_t3[threadIdx.x] = 0.f;
    }
    if (threadIdx.x == 0) {
        int odd = 0;
        #pragma unroll 1
        for (int i = 1; i < 512; i += 2) odd |= raw[i];
        is64 = (odd == 0) ? 1 : 0;
    }
    __syncthreads();
    int e = blockIdx.x * blockDim.x + threadIdx.x;
    if (e < EE) {
        if (is64) { g_src[e] = raw[2 * e];        g_tgt[e] = raw[2 * (EE + e)]; }
        else      { g_src[e] = raw[e];            g_tgt[e] = raw[EE + e]; }
    }
}

// ---------------- encoder ----------------
__global__ void enc_kernel(const float* __restrict__ x,
                           const float* __restrict__ w,
                           const float* __restrict__ b) {
    int tid = blockIdx.x * blockDim.x + threadIdx.x;
    int i = tid >> 6, f = tid & 63;
    float acc = b[f];
    #pragma unroll
    for (int k = 0; k < 4; k++) acc = fmaf(x[i * 4 + k], w[k * 64 + f], acc);
    g_h[tid] = acc;
    g_agg[tid] = 0.f;
}

// ================= PQ kernel (+optional fused instance-norm apply) =================
// smem: sA 128x68=8704 ; sB 128x144=18432 ; mean/rstd 128 -> 27264 floats = 109056 B, 2/SM
#define PQ_A   0
#define PQ_B   8704
#define PQ_MN  27136
#define PQ_RS  27200
#define PQ_FLOATS 27264
#define PQ_BYTES  (PQ_FLOATS * 4)

__global__ void __launch_bounds__(256) pq_kernel(const float* __restrict__ w1,
                                                 const float* __restrict__ b1,
                                                 int do_norm) {
    extern __shared__ float sm[];
    float* sA = sm + PQ_A;
    float* sB = sm + PQ_B;
    int tid = threadIdx.x;
    int nb0 = blockIdx.x * 128;
    int g = nb0 >> 11;

    // stage B' = 64(k) x 128(n) interleaved: n<64 -> W1a[k][n]; n>=64 -> W1b[k][n-64]
    for (int i = tid; i < 8192; i += 256) {
        int k = i >> 7, n = i & 127;
        float w = w1[((n < 64) ? k : (64 + k)) * 64 + (n & 63)];
        uint32_t h, l; split_tf32(w, h, l);
        int pos = n * 144 + ((k >> 3) << 4) + ((k & 3) << 2) + ((k >> 2) & 1);
        sB[pos]     = __uint_as_float(h);
        sB[pos + 2] = __uint_as_float(l);
    }
    if (do_norm && tid < 64) {
        float mean = g_sum[g * 64 + tid] * (1.f / NSAMPLES);
        float var  = g_sqs[g * 64 + tid] * (1.f / NSAMPLES) - mean * mean;
        sm[PQ_MN + tid] = mean;
        sm[PQ_RS + tid] = rsqrtf(var + EPSI);
    }
    __syncthreads();

    #pragma unroll
    for (int it = 0; it < 8; it++) {
        int idx = tid + it * 256;
        int row = idx >> 4, f4 = idx & 15;
        float4 v = *(const float4*)&g_h[(nb0 + row) * 64 + f4 * 4];
        if (do_norm) {
            float4 mn = *(const float4*)&sm[PQ_MN + f4 * 4];
            float4 rs = *(const float4*)&sm[PQ_RS + f4 * 4];
            v.x = (v.x - mn.x) * rs.x; v.y = (v.y - mn.y) * rs.y;
            v.z = (v.z - mn.z) * rs.z; v.w = (v.w - mn.w) * rs.w;
            *(float4*)&g_h[(nb0 + row) * 64 + f4 * 4] = v;   // materialize normalized h
        }
        *(float4*)&sA[row * 68 + f4 * 4] = v;
    }
    __syncthreads();

    int warp = tid >> 5, lane = tid & 31, gid = lane >> 2, tig = lane & 3;
    int mr = (warp >> 1) * 32, n0 = (warp & 1) * 64;

    float acc[2][8][4] = {};
    gemm_sp2<64, 68, 8, 144>(sA, sB, mr, n0, lane, acc);

    #pragma unroll
    for (int f = 0; f < 2; f++) {
        int r0 = mr + f * 16 + gid;
        #pragma unroll
        for (int nt = 0; nt < 8; nt++) {
            int col = n0 + nt * 8 + 2 * tig;
            float bb0 = (col < 64) ? __ldg(b1 + col)     : 0.f;
            float bb1 = (col < 64) ? __ldg(b1 + col + 1) : 0.f;
            g_PQ[(nb0 + r0) * 128 + col]         = acc[f][nt][0] + bb0;
            g_PQ[(nb0 + r0) * 128 + col + 1]     = acc[f][nt][1] + bb1;
            g_PQ[(nb0 + r0 + 8) * 128 + col]     = acc[f][nt][2] + bb0;
            g_PQ[(nb0 + r0 + 8) * 128 + col + 1] = acc[f][nt][3] + bb1;
        }
    }
}

// ================= edge kernel: fully-interleaved A and B, register-direct scatter ======
// smem: sA 128x144=18432 (interleaved hi/lo), sB 64x144=9216, b2 64
//       = 27712 floats = 110848 B -> 2 blocks/SM
#define E_A    0
#define E_B    18432
#define E_BI2  27648
#define E_FLOATS 27712
#define E_BYTES  (E_FLOATS * 4)

__global__ void __launch_bounds__(256) edge_mma_kernel(const float* __restrict__ w2,
                                                       const float* __restrict__ b2) {
    extern __shared__ float sm[];
    float* sA = sm + E_A;
    float* sB = sm + E_B;
    int tid = threadIdx.x;

    if (blockIdx.x == 0) {
        for (int i = tid; i < NBATCH * NHID; i += 256) { g_sum[i] = 0.f; g_sqs[i] = 0.f; }
    }
    stage_Bi<64, 144>(sB, w2);
    if (tid < 64) sm[E_BI2 + tid] = b2[tid];

    int warp = tid >> 5, lane = tid & 31, gid = lane >> 2, tig = lane & 3;
    int mr = (warp >> 1) * 32, n0 = (warp & 1) * 32;

    for (int tile = blockIdx.x; tile < EE / 128; tile += gridDim.x) {
        int e0 = tile * 128;
        __syncthreads();   // staging visible / previous tile's gemm reads complete
        // gather + relu + split into interleaved layout: 128 rows x 8 kg
        #pragma unroll
        for (int it = 0; it < 4; it++) {
            int idx = tid + it * 256;
            int row = idx >> 3, kg = idx & 7;
            int t = g_tgt[e0 + row], s = g_src[e0 + row];
            float4 pa = *(const float4*)&g_PQ[t * 128 + kg * 8];
            float4 pb = *(const float4*)&g_PQ[t * 128 + kg * 8 + 4];
            float4 qa = *(const float4*)&g_PQ[s * 128 + 64 + kg * 8];
            float4 qb = *(const float4*)&g_PQ[s * 128 + 64 + kg * 8 + 4];
            uint32_t h[8], l[8];
            split_tf32(fmaxf(pa.x + qa.x, 0.f), h[0], l[0]);
            split_tf32(fmaxf(pa.y + qa.y, 0.f), h[1], l[1]);
            split_tf32(fmaxf(pa.z + qa.z, 0.f), h[2], l[2]);
            split_tf32(fmaxf(pa.w + qa.w, 0.f), h[3], l[3]);
            split_tf32(fmaxf(pb.x + qb.x, 0.f), h[4], l[4]);
            split_tf32(fmaxf(pb.y + qb.y, 0.f), h[5], l[5]);
            split_tf32(fmaxf(pb.z + qb.z, 0.f), h[6], l[6]);
            split_tf32(fmaxf(pb.w + qb.w, 0.f), h[7], l[7]);
            int base = row * 144 + kg * 16;
            // slot tig = {h(tig), h(tig+4), l(tig), l(tig+4)}
            *(float4*)&sA[base]      = make_float4(__uint_as_float(h[0]), __uint_as_float(h[4]),
                                                   __uint_as_float(l[0]), __uint_as_float(l[4]));
            *(float4*)&sA[base + 4]  = make_float4(__uint_as_float(h[1]), __uint_as_float(h[5]),
                                                   __uint_as_float(l[1]), __uint_as_float(l[5]));
            *(float4*)&sA[base + 8]  = make_float4(__uint_as_float(h[2]), __uint_as_float(h[6]),
                                                   __uint_as_float(l[2]), __uint_as_float(l[6]));
            *(float4*)&sA[base + 12] = make_float4(__uint_as_float(h[3]), __uint_as_float(h[7]),
                                                   __uint_as_float(l[3]), __uint_as_float(l[7]));
        }
        __syncthreads();
        float acc[2][4][4] = {};
        gemm_ii<64, 144, 4, 144>(sA, sB, mr, n0, lane, acc);
        // register-direct scatter: bias + relu + red.v2
        int t0 = g_tgt[e0 + mr + gid];
        int t1 = g_tgt[e0 + mr + gid + 8];
        int t2 = g_tgt[e0 + mr + 16 + gid];
        int t3 = g_tgt[e0 + mr + 24 + gid];
        #pragma unroll
        for (int nt = 0; nt < 4; nt++) {
            int col = n0 + nt * 8 + 2 * tig;
            float bb0 = sm[E_BI2 + col], bb1 = sm[E_BI2 + col + 1];
            red_add_v2(&g_agg[t0 * 64 + col],
                       fmaxf(acc[0][nt][0] + bb0, 0.f), fmaxf(acc[0][nt][1] + bb1, 0.f));
            red_add_v2(&g_agg[t1 * 64 + col],
                       fmaxf(acc[0][nt][2] + bb0, 0.f), fmaxf(acc[0][nt][3] + bb1, 0.f));
            red_add_v2(&g_agg[t2 * 64 + col],
                       fmaxf(acc[1][nt][0] + bb0, 0.f), fmaxf(acc[1][nt][1] + bb1, 0.f));
            red_add_v2(&g_agg[t3 * 64 + col],
                       fmaxf(acc[1][nt][2] + bb0, 0.f), fmaxf(acc[1][nt][3] + bb1, 0.f));
        }
    }
}

// ================= node update kernel (K=128 GEMM1, K=64 GEMM2) + fused norm stats ============
// smem: sA 128x132=16896; sM 128x68=8704; B1 64x272=17408; B2 64x144=9216; biases 128
//       = 52352 floats = 209408 B -> 1 block/SM
#define U_A    0
#define U_M    16896
#define U_B1   25600
#define U_B2   43008
#define U_BI1  52224
#define U_BI2  52288
#define U_FLOATS 52352
#define U_BYTES  (U_FLOATS * 4)

__global__ void __launch_bounds__(256) upd_mma_kernel(const float* __restrict__ w1,
                                                      const float* __restrict__ b1,
                                                      const float* __restrict__ w2,
                                                      const float* __restrict__ b2) {
    extern __shared__ float sm[];
    float* sA = sm + U_A;
    float* sM = sm + U_M;
    int tid = threadIdx.x;
    stage_Bi<128, 272>(sm + U_B1, w1);
    stage_Bi<64, 144>(sm + U_B2, w2);
    if (tid < 64) { sm[U_BI1 + tid] = b1[tid]; sm[U_BI2 + tid] = b2[tid]; }

    int warp = tid >> 5, lane = tid & 31, gid = lane >> 2, tig = lane & 3;
    int mr = (warp >> 1) * 32, n0 = (warp & 1) * 32;
    int nb0 = blockIdx.x * 128;

    #pragma unroll
    for (int it = 0; it < 16; it++) {
        int i = tid + it * 256;
        int e = i >> 5, part = i & 31;
        int node = nb0 + e;
        float4 v;
        if (part < 16) {
            v = *(const float4*)&g_h[node * 64 + part * 4];
        } else {
            float4* ap = (float4*)&g_agg[node * 64 + (part & 15) * 4];
            v = *ap;
            *ap = make_float4(0.f, 0.f, 0.f, 0.f);
        }
        *(float4*)&sA[e * 132 + part * 4] = v;
    }
    __syncthreads();
    float acc[2][4][4] = {};
    gemm_sp2<128, 132, 4, 272>(sA, sm + U_B1, mr, n0, lane, acc);
    #pragma unroll
    for (int f = 0; f < 2; f++) {
        int r0 = mr + f * 16 + gid;
        #pragma unroll
        for (int nt = 0; nt < 4; nt++) {
            int col = n0 + nt * 8 + 2 * tig;
            float bb0 = sm[U_BI1 + col], bb1 = sm[U_BI1 + col + 1];
            sM[r0 * 68 + col]           = fmaxf(acc[f][nt][0] + bb0, 0.f);
            sM[r0 * 68 + col + 1]       = fmaxf(acc[f][nt][1] + bb1, 0.f);
            sM[(r0 + 8) * 68 + col]     = fmaxf(acc[f][nt][2] + bb0, 0.f);
            sM[(r0 + 8) * 68 + col + 1] = fmaxf(acc[f][nt][3] + bb1, 0.f);
        }
    }
    __syncthreads();
    float acc2[2][4][4] = {};
    gemm_sp2<64, 68, 4, 144>(sM, sm + U_B2, mr, n0, lane, acc2);
    #pragma unroll
    for (int f = 0; f < 2; f++) {
        int r0 = mr + f * 16 + gid;
        #pragma unroll
        for (int nt = 0; nt < 4; nt++) {
            int col = n0 + nt * 8 + 2 * tig;
            float bb0 = sm[U_BI2 + col], bb1 = sm[U_BI2 + col + 1];
            sA[r0 * 68 + col]           = fmaxf(acc2[f][nt][0] + bb0, 0.f);
            sA[r0 * 68 + col + 1]       = fmaxf(acc2[f][nt][1] + bb1, 0.f);
            sA[(r0 + 8) * 68 + col]     = fmaxf(acc2[f][nt][2] + bb0, 0.f);
            sA[(r0 + 8) * 68 + col + 1] = fmaxf(acc2[f][nt][3] + bb1, 0.f);
        }
    }
    __syncthreads();
    // store + fused per-feature stats (tile is within one graph: 2048 % 128 == 0)
    int f4 = tid & 15;
    float4 s = make_float4(0.f, 0.f, 0.f, 0.f);
    float4 q = make_float4(0.f, 0.f, 0.f, 0.f);
    #pragma unroll
    for (int it = 0; it < 8; it++) {
        int idx = tid + it * 256;
        int row = idx >> 4;
        float4 v = *(const float4*)&sA[row * 68 + f4 * 4];
        *(float4*)&g_h[(nb0 + row) * 64 + f4 * 4] = v;
        s.x += v.x; s.y += v.y; s.z += v.z; s.w += v.w;
        q.x = fmaf(v.x, v.x, q.x); q.y = fmaf(v.y, v.y, q.y);
        q.z = fmaf(v.z, v.z, q.z); q.w = fmaf(v.w, v.w, q.w);
    }
    int g = nb0 >> 11;
    red_add_v4(&g_sum[g * 64 + f4 * 4], s);
    red_add_v4(&g_sqs[g * 64 + f4 * 4], q);
}

// ---------------- instance norm: standalone apply (final layer only) ----------------
__global__ void norm_apply_kernel() {
    int g = blockIdx.x >> 3, sl = blockIdx.x & 7;
    int tid = threadIdx.x;
    __shared__ float smean[64], srstd[64];
    if (tid < 64) {
        float mean = g_sum[g * 64 + tid] * (1.f / NSAMPLES);
        float var  = g_sqs[g * 64 + tid] * (1.f / NSAMPLES) - mean * mean;
        smean[tid] = mean;
        srstd[tid] = rsqrtf(var + EPSI);
    }
    __syncthreads();
    int f4 = tid & 15, rc = tid >> 4;
    int row0 = g * NSAMPLES + sl * 256 + rc * 16;
    float4 mn = *(const float4*)&smean[f4 * 4];
    float4 rs = *(const float4*)&srstd[f4 * 4];
    #pragma unroll
    for (int r = 0; r < 16; r++) {
        float4* p = (float4*)&g_h[(row0 + r) * 64 + f4 * 4];
        float4 v = *p;
        v.x = (v.x - mn.x) * rs.x; v.y = (v.y - mn.y) * rs.y;
        v.z = (v.z - mn.z) * rs.z; v.w = (v.w - mn.w) * rs.w;
        *p = v;
    }
}

// ---------------- decoder + t2 term ----------------
__global__ void dec_kernel(const float* __restrict__ w, const float* __restrict__ b) {
    int i = blockIdx.x * blockDim.x + threadIdx.x;
    const float* hr = &g_h[i * 64];
    float a0 = b[0], a1 = b[1], a2 = b[2], a3 = b[3];
    #pragma unroll 8
    for (int k = 0; k < 64; k++) {
        float hv = hr[k];
        a0 = fmaf(hv, w[k * 4 + 0], a0);
        a1 = fmaf(hv, w[k * 4 + 1], a1);
        a2 = fmaf(hv, w[k * 4 + 2], a2);
        a3 = fmaf(hv, w[k * 4 + 3], a3);
    }
    a0 = 1.f / (1.f + expf(-a0));
    a1 = 1.f / (1.f + expf(-a1));
    a2 = 1.f / (1.f + expf(-a2));
    a3 = 1.f / (1.f + expf(-a3));
    g_X[i * 4 + 0] = a0; g_X[i * 4 + 1] = a1;
    g_X[i * 4 + 2] = a2; g_X[i * 4 + 3] = a3;
    float pr = (1.f - a0 * a0) * (1.f - a1 * a1) * (1.f - a2 * a2) * (1.f - a3 * a3);
    #pragma unroll
    for (int off = 16; off > 0; off >>= 1)
        pr += __shfl_down_sync(0xffffffffu, pr, off);
    if ((threadIdx.x & 31) == 0) atomicAdd(&g_t2[i >> 11], pr);
}

// ---------------- t3 pairwise term ----------------
__global__ void t3_kernel() {
    int b = blockIdx.x;
    int g = b >> 6, ic = (b >> 2) & 15, jc = b & 3;
    int tid = threadIdx.x;         // 128
    __shared__ float4 sX[512];
    const float4* Xg = (const float4*)&g_X[(g * NSAMPLES) * 4];
    for (int j = tid; j < 512; j += 128) sX[j] = Xg[jc * 512 + j];
    __syncthreads();
    float4 xi = Xg[ic * 128 + tid];
    float acc = 0.f;
    #pragma unroll 4
    for (int j = 0; j < 512; j++) {
        float4 xj = sX[j];
        float p = (1.f - fmaxf(xi.x, xj.x)) * (1.f - fmaxf(xi.y, xj.y)) *
                  (1.f - fmaxf(xi.z, xj.z)) * (1.f - fmaxf(xi.w, xj.w));
        acc += p;
    }
    __shared__ float red[128];
    red[tid] = acc; __syncthreads();
    for (int off = 64; off > 0; off >>= 1) {
        if (tid < off) red[tid] += red[tid + off];
        __syncthreads();
    }
    if (tid == 0) atomicAdd(&g_t3[g], red[0]);
}

// ---------------- emit ----------------
__global__ void emit_kernel(float* __restrict__ out, int out_size) {
    int tid = blockIdx.x * blockDim.x + threadIdx.x;
    float loss = 0.f;
    if (tid == 0) {
        const float t1 = 1.0f / 81.0f;
        #pragma unroll
        for (int g = 0; g < NBATCH; g++) {
            float l = t1 - g_t2[g] * (2.0f / 32768.0f)
                         + g_t3[g] * (1.0f / (2048.f * 2048.f));
            loss += l;
        }
        loss *= (1.0f / NBATCH);
    }
    if (out_size == NN * DIMX) {
        if (tid < NN * DIMX) out[tid] = g_X[tid];
    } else {
        if (tid == 0) out[0] = loss;
        int idx = tid - 1;
        if (idx >= 0 && idx < NN * DIMX && (idx + 1) < out_size) out[1 + idx] = g_X[idx];
    }
}

// ---------------- launch ----------------
extern "C" void kernel_launch(void* const* d_in, const int* in_sizes, int n_in,
                              void* d_out, int out_size) {
    const float* x     = (const float*)d_in[0];
    const int*   eiraw = (const int*)  d_in[1];
    const float* enc_w = (const float*)d_in[2];
    const float* enc_b = (const float*)d_in[3];
    const float* m1_w  = (const float*)d_in[4];
    const float* m1_b  = (const float*)d_in[5];
    const float* m2_w  = (const float*)d_in[6];
    const float* m2_b  = (const float*)d_in[7];
    const float* u1_w  = (const float*)d_in[8];
    const float* u1_b  = (const float*)d_in[9];
    const float* u2_w  = (const float*)d_in[10];
    const float* u2_b  = (const float*)d_in[11];
    const float* dec_w = (const float*)d_in[12];
    const float* dec_b = (const float*)d_in[13];
    float* out = (float*)d_out;

    (void)cudaFuncSetAttribute(pq_kernel,       cudaFuncAttributeMaxDynamicSharedMemorySize, PQ_BYTES);
    (void)cudaFuncSetAttribute(edge_mma_kernel, cudaFuncAttributeMaxDynamicSharedMemorySize, E_BYTES);
    (void)cudaFuncSetAttribute(upd_mma_kernel,  cudaFuncAttributeMaxDynamicSharedMemorySize, U_BYTES);

    cvt_edges_kernel<<<(EE + 255) / 256, 256>>>(eiraw);
    enc_kernel<<<NN * NHID / 256, 256>>>(x, enc_w, enc_b);
    for (int l = 0; l < NLAYERS; l++) {
        // pq(l) also applies instance-norm of layer l-1 (stats from upd(l-1))
        pq_kernel<<<NN / 128, 256, PQ_BYTES>>>(m1_w + l * 128 * 64, m1_b + l * 64, l > 0);
        edge_mma_kernel<<<296, 256, E_BYTES>>>(m2_w + l * 64 * 64, m2_b + l * 64);
        upd_mma_kernel<<<NN / 128, 256, U_BYTES>>>(
            u1_w + l * 128 * 64, u1_b + l * 64, u2_w + l * 64 * 64, u2_b + l * 64);
    }
    norm_apply_kernel<<<64, 256>>>();   // final layer's norm (for decoder)
    dec_kernel<<<NN / 256, 256>>>(dec_w, dec_b);
    t3_kernel<<<512, 128>>>();
    emit_kernel<<<(NN * DIMX + 1 + 255) / 256, 256>>>(out, out_size);
}

// round 17
// speedup vs baseline: 1.1170x; 1.1170x over previous
#include <cuda_runtime.h>
#include <math.h>
#include <stdint.h>

#define NBATCH   8
#define NSAMPLES 2048
#define DIMX     4
#define NHID     64
#define NLAYERS  3
#define NN       (NBATCH * NSAMPLES)     // 16384 nodes
#define EE       (NN * 16)               // 262144 edges
#define EPSI     1e-5f

// ---------------- static device scratch ----------------
__device__ float g_h[NN * NHID];
__device__ float g_agg[NN * NHID];
__device__ __align__(16) float g_PQ[NN * 128];   // [P|Q] per node (P includes b1)
__device__ __align__(16) float g_X[NN * DIMX];
__device__ int   g_src[EE];
__device__ int   g_tgt[EE];
__device__ float g_t2[NBATCH];
__device__ float g_t3[NBATCH];
__device__ float g_sum[NBATCH * NHID];
__device__ float g_sqs[NBATCH * NHID];

// ---------------- tf32 helpers ----------------
// hi = round-to-nearest tf32; lo = raw fp32 residual (HW truncates low mantissa bits)
__device__ __forceinline__ void split_tf32(float x, uint32_t& hi, uint32_t& lo) {
    uint32_t h;
    asm("cvt.rna.tf32.f32 %0, %1;" : "=r"(h) : "f"(x));
    lo = __float_as_uint(x - __uint_as_float(h));
    hi = h;
}

__device__ __forceinline__ void mma_tf32(float c[4], const uint32_t a[4], const uint32_t b[2]) {
    asm volatile(
        "mma.sync.aligned.m16n8k8.row.col.f32.tf32.tf32.f32 "
        "{%0,%1,%2,%3}, {%4,%5,%6,%7}, {%8,%9}, {%0,%1,%2,%3};"
        : "+f"(c[0]), "+f"(c[1]), "+f"(c[2]), "+f"(c[3])
        : "r"(a[0]), "r"(a[1]), "r"(a[2]), "r"(a[3]), "r"(b[0]), "r"(b[1]));
}

__device__ __forceinline__ void red_add_v4(float* p, float4 v) {
    asm volatile("red.global.add.v4.f32 [%0], {%1,%2,%3,%4};"
                 :: "l"(p), "f"(v.x), "f"(v.y), "f"(v.z), "f"(v.w) : "memory");
}

__device__ __forceinline__ void red_add_v2(float* p, float a, float b) {
    asm volatile("red.global.add.v2.f32 [%0], {%1,%2};"
                 :: "l"(p), "f"(a), "f"(b) : "memory");
}

// ---------------- paired-transposed B staging (float2-pair layout, R14-proven) ----------------
// w: [K][64] row-major. dst: [64 n][LDB] with k-pair permute: within each 8-k block,
// slot = 2*(k&3) + ((k>>2)&1), so (k+tig, k+tig+4) is one float2 at k0+2*tig.
template<int K, int LDB>
__device__ __forceinline__ void stage_Bt(float* dh, float* dl, const float* __restrict__ w) {
    int tid = threadIdx.x;
    for (int i = tid; i < K * 64; i += 256) {
        int k = i >> 6, n = i & 63;
        uint32_t h, l; split_tf32(w[i], h, l);
        int pos = n * LDB + (k & ~7) + ((k & 3) << 1) + ((k >> 2) & 1);
        dh[pos] = __uint_as_float(h);
        dl[pos] = __uint_as_float(l);
    }
}

// ---------------- GEMM: A fp32 (split in loop), B paired-transposed hi/lo ----------------
template<int K, int LDA, int NT, int LDB>
__device__ __forceinline__ void gemm_sp(const float* __restrict__ sA,
                                        const float* __restrict__ sBh,
                                        const float* __restrict__ sBl,
                                        int mr, int n0, int lane, float acc[2][NT][4]) {
    int gid = lane >> 2, tig = lane & 3;
    #pragma unroll
    for (int k0 = 0; k0 < K; k0 += 8) {
        uint32_t ah[2][4], al[2][4];
        #pragma unroll
        for (int f = 0; f < 2; f++) {
            int r0 = mr + f * 16 + gid;
            split_tf32(sA[r0 * LDA + k0 + tig],           ah[f][0], al[f][0]);
            split_tf32(sA[(r0 + 8) * LDA + k0 + tig],     ah[f][1], al[f][1]);
            split_tf32(sA[r0 * LDA + k0 + tig + 4],       ah[f][2], al[f][2]);
            split_tf32(sA[(r0 + 8) * LDA + k0 + tig + 4], ah[f][3], al[f][3]);
        }
        #pragma unroll
        for (int nt = 0; nt < NT; nt++) {
            int c0 = n0 + nt * 8 + gid;
            float2 bh2 = *(const float2*)&sBh[c0 * LDB + k0 + 2 * tig];
            float2 bl2 = *(const float2*)&sBl[c0 * LDB + k0 + 2 * tig];
            uint32_t bh[2] = { __float_as_uint(bh2.x), __float_as_uint(bh2.y) };
            uint32_t bl[2] = { __float_as_uint(bl2.x), __float_as_uint(bl2.y) };
            #pragma unroll
            for (int f = 0; f < 2; f++) {
                mma_tf32(acc[f][nt], al[f], bh);
                mma_tf32(acc[f][nt], ah[f], bl);
                mma_tf32(acc[f][nt], ah[f], bh);
            }
        }
    }
}

// ---------------- GEMM (16-row warp tile): A pre-split paired, B paired-transposed ----------
template<int K, int LDA, int NT, int LDB>
__device__ __forceinline__ void gemm_pp1(const float* __restrict__ sAh,
                                         const float* __restrict__ sAl,
                                         const float* __restrict__ sBh,
                                         const float* __restrict__ sBl,
                                         int mr, int n0, int lane, float acc[NT][4]) {
    int gid = lane >> 2, tig = lane & 3;
    #pragma unroll
    for (int k0 = 0; k0 < K; k0 += 8) {
        int r0 = mr + gid;
        float2 h0 = *(const float2*)&sAh[r0 * LDA + k0 + 2 * tig];
        float2 h1 = *(const float2*)&sAh[(r0 + 8) * LDA + k0 + 2 * tig];
        float2 l0 = *(const float2*)&sAl[r0 * LDA + k0 + 2 * tig];
        float2 l1 = *(const float2*)&sAl[(r0 + 8) * LDA + k0 + 2 * tig];
        uint32_t ah[4] = { __float_as_uint(h0.x), __float_as_uint(h1.x),
                           __float_as_uint(h0.y), __float_as_uint(h1.y) };
        uint32_t al[4] = { __float_as_uint(l0.x), __float_as_uint(l1.x),
                           __float_as_uint(l0.y), __float_as_uint(l1.y) };
        #pragma unroll
        for (int nt = 0; nt < NT; nt++) {
            int c0 = n0 + nt * 8 + gid;
            float2 bh2 = *(const float2*)&sBh[c0 * LDB + k0 + 2 * tig];
            float2 bl2 = *(const float2*)&sBl[c0 * LDB + k0 + 2 * tig];
            uint32_t bh[2] = { __float_as_uint(bh2.x), __float_as_uint(bh2.y) };
            uint32_t bl[2] = { __float_as_uint(bl2.x), __float_as_uint(bl2.y) };
            mma_tf32(acc[nt], al, bh);
            mma_tf32(acc[nt], ah, bl);
            mma_tf32(acc[nt], ah, bh);
        }
    }
}

// ---------------- edge index decode (+ t2/t3 zeroing) ----------------
__global__ void cvt_edges_kernel(const int* __restrict__ raw) {
    __shared__ int is64;
    if (blockIdx.x == 0 && threadIdx.x < NBATCH) {
        g_t2[threadIdx.x] = 0.f; g_t3[threadIdx.x] = 0.f;
    }
    if (threadIdx.x == 0) {
        int odd = 0;
        #pragma unroll 1
        for (int i = 1; i < 512; i += 2) odd |= raw[i];
        is64 = (odd == 0) ? 1 : 0;
    }
    __syncthreads();
    int e = blockIdx.x * blockDim.x + threadIdx.x;
    if (e < EE) {
        if (is64) { g_src[e] = raw[2 * e];        g_tgt[e] = raw[2 * (EE + e)]; }
        else      { g_src[e] = raw[e];            g_tgt[e] = raw[EE + e]; }
    }
}

// ---------------- encoder ----------------
__global__ void enc_kernel(const float* __restrict__ x,
                           const float* __restrict__ w,
                           const float* __restrict__ b) {
    int tid = blockIdx.x * blockDim.x + threadIdx.x;
    int i = tid >> 6, f = tid & 63;
    float acc = b[f];
    #pragma unroll
    for (int k = 0; k < 4; k++) acc = fmaf(x[i * 4 + k], w[k * 64 + f], acc);
    g_h[tid] = acc;
    g_agg[tid] = 0.f;
}

// ================= PQ kernel (+optional fused instance-norm apply) =================
// smem: sA 128x68=8704 ; Bh 128x72=9216 ; Bl 9216 ; mean/rstd 128 -> 108.5 KB, 2/SM
#define PQ_A   0
#define PQ_BH  8704
#define PQ_BL  17920
#define PQ_MN  27136
#define PQ_RS  27200
#define PQ_FLOATS 27264
#define PQ_BYTES  (PQ_FLOATS * 4)

__global__ void __launch_bounds__(256) pq_kernel(const float* __restrict__ w1,
                                                 const float* __restrict__ b1,
                                                 int do_norm) {
    extern __shared__ float sm[];
    float* sA  = sm + PQ_A;
    float* sBh = sm + PQ_BH;
    float* sBl = sm + PQ_BL;
    int tid = threadIdx.x;
    int nb0 = blockIdx.x * 128;
    int g = nb0 >> 11;

    // stage B' = 64(k) x 128(n) transposed + pair-permuted
    for (int i = tid; i < 8192; i += 256) {
        int k = i >> 7, n = i & 127;
        float w = w1[((n < 64) ? k : (64 + k)) * 64 + (n & 63)];
        uint32_t h, l; split_tf32(w, h, l);
        int pos = n * 72 + (k & ~7) + ((k & 3) << 1) + ((k >> 2) & 1);
        sBh[pos] = __uint_as_float(h);
        sBl[pos] = __uint_as_float(l);
    }
    if (do_norm && tid < 64) {
        float mean = g_sum[g * 64 + tid] * (1.f / NSAMPLES);
        float var  = g_sqs[g * 64 + tid] * (1.f / NSAMPLES) - mean * mean;
        sm[PQ_MN + tid] = mean;
        sm[PQ_RS + tid] = rsqrtf(var + EPSI);
    }
    __syncthreads();

    #pragma unroll
    for (int it = 0; it < 8; it++) {
        int idx = tid + it * 256;
        int row = idx >> 4, f4 = idx & 15;
        float4 v = *(const float4*)&g_h[(nb0 + row) * 64 + f4 * 4];
        if (do_norm) {
            float4 mn = *(const float4*)&sm[PQ_MN + f4 * 4];
            float4 rs = *(const float4*)&sm[PQ_RS + f4 * 4];
            v.x = (v.x - mn.x) * rs.x; v.y = (v.y - mn.y) * rs.y;
            v.z = (v.z - mn.z) * rs.z; v.w = (v.w - mn.w) * rs.w;
            *(float4*)&g_h[(nb0 + row) * 64 + f4 * 4] = v;   // materialize normalized h
        }
        *(float4*)&sA[row * 68 + f4 * 4] = v;
    }
    __syncthreads();

    int warp = tid >> 5, lane = tid & 31, gid = lane >> 2, tig = lane & 3;
    int mr = (warp >> 1) * 32, n0 = (warp & 1) * 64;

    float acc[2][8][4] = {};
    gemm_sp<64, 68, 8, 72>(sA, sBh, sBl, mr, n0, lane, acc);

    #pragma unroll
    for (int f = 0; f < 2; f++) {
        int r0 = mr + f * 16 + gid;
        #pragma unroll
        for (int nt = 0; nt < 8; nt++) {
            int col = n0 + nt * 8 + 2 * tig;
            float bb0 = (col < 64) ? __ldg(b1 + col)     : 0.f;
            float bb1 = (col < 64) ? __ldg(b1 + col + 1) : 0.f;
            g_PQ[(nb0 + r0) * 128 + col]         = acc[f][nt][0] + bb0;
            g_PQ[(nb0 + r0) * 128 + col + 1]     = acc[f][nt][1] + bb1;
            g_PQ[(nb0 + r0 + 8) * 128 + col]     = acc[f][nt][2] + bb0;
            g_PQ[(nb0 + r0 + 8) * 128 + col + 1] = acc[f][nt][3] + bb1;
        }
    }
}

// ================= edge kernel: 64-edge tiles, 3 blocks/SM, register-direct scatter ======
// smem: sMh 64x72=4608, sMl 4608, B2h 4608, B2l 4608, b2 64 = 18496 floats = 73984 B -> 3/SM
#define E_MH   0
#define E_ML   4608
#define E_B2H  9216
#define E_B2L  13824
#define E_BI2  18432
#define E_FLOATS 18496
#define E_BYTES  (E_FLOATS * 4)

__global__ void __launch_bounds__(256, 3) edge_mma_kernel(const float* __restrict__ w2,
                                                          const float* __restrict__ b2) {
    extern __shared__ float sm[];
    float* sMh = sm + E_MH;
    float* sMl = sm + E_ML;
    int tid = threadIdx.x;

    if (blockIdx.x == 0) {
        for (int i = tid; i < NBATCH * NHID; i += 256) { g_sum[i] = 0.f; g_sqs[i] = 0.f; }
    }
    stage_Bt<64, 72>(sm + E_B2H, sm + E_B2L, w2);
    if (tid < 64) sm[E_BI2 + tid] = b2[tid];

    int warp = tid >> 5, lane = tid & 31, gid = lane >> 2, tig = lane & 3;
    int mr = (warp >> 1) * 16, n0 = (warp & 1) * 32;   // 4 m-slots x 2 n-slots over 64x64

    for (int tile = blockIdx.x; tile < EE / 64; tile += gridDim.x) {
        int e0 = tile * 64;
        __syncthreads();   // staging visible / previous tile's gemm reads complete
        // gather + relu + pre-split into paired layout: 64 rows x 8 kg
        #pragma unroll
        for (int it = 0; it < 2; it++) {
            int idx = tid + it * 256;
            int row = idx >> 3, kg = idx & 7;
            int t = g_tgt[e0 + row], s = g_src[e0 + row];
            float4 pa = *(const float4*)&g_PQ[t * 128 + kg * 8];
            float4 pb = *(const float4*)&g_PQ[t * 128 + kg * 8 + 4];
            float4 qa = *(const float4*)&g_PQ[s * 128 + 64 + kg * 8];
            float4 qb = *(const float4*)&g_PQ[s * 128 + 64 + kg * 8 + 4];
            uint32_t h[8], l[8];
            split_tf32(fmaxf(pa.x + qa.x, 0.f), h[0], l[0]);
            split_tf32(fmaxf(pa.y + qa.y, 0.f), h[1], l[1]);
            split_tf32(fmaxf(pa.z + qa.z, 0.f), h[2], l[2]);
            split_tf32(fmaxf(pa.w + qa.w, 0.f), h[3], l[3]);
            split_tf32(fmaxf(pb.x + qb.x, 0.f), h[4], l[4]);
            split_tf32(fmaxf(pb.y + qb.y, 0.f), h[5], l[5]);
            split_tf32(fmaxf(pb.z + qb.z, 0.f), h[6], l[6]);
            split_tf32(fmaxf(pb.w + qb.w, 0.f), h[7], l[7]);
            int base = row * 72 + kg * 8;
            // permuted order: [k0, k0+4, k0+1, k0+5 | k0+2, k0+6, k0+3, k0+7]
            *(float4*)&sMh[base]     = make_float4(__uint_as_float(h[0]), __uint_as_float(h[4]),
                                                   __uint_as_float(h[1]), __uint_as_float(h[5]));
            *(float4*)&sMh[base + 4] = make_float4(__uint_as_float(h[2]), __uint_as_float(h[6]),
                                                   __uint_as_float(h[3]), __uint_as_float(h[7]));
            *(float4*)&sMl[base]     = make_float4(__uint_as_float(l[0]), __uint_as_float(l[4]),
                                                   __uint_as_float(l[1]), __uint_as_float(l[5]));
            *(float4*)&sMl[base + 4] = make_float4(__uint_as_float(l[2]), __uint_as_float(l[6]),
                                                   __uint_as_float(l[3]), __uint_as_float(l[7]));
        }
        __syncthreads();
        float acc[4][4] = {};
        gemm_pp1<64, 72, 4, 72>(sMh, sMl, sm + E_B2H, sm + E_B2L, mr, n0, lane, acc);
        // register-direct scatter: bias + relu + red.v2
        int t0 = g_tgt[e0 + mr + gid];
        int t1 = g_tgt[e0 + mr + gid + 8];
        #pragma unroll
        for (int nt = 0; nt < 4; nt++) {
            int col = n0 + nt * 8 + 2 * tig;
            float bb0 = sm[E_BI2 + col], bb1 = sm[E_BI2 + col + 1];
            red_add_v2(&g_agg[t0 * 64 + col],
                       fmaxf(acc[nt][0] + bb0, 0.f), fmaxf(acc[nt][1] + bb1, 0.f));
            red_add_v2(&g_agg[t1 * 64 + col],
                       fmaxf(acc[nt][2] + bb0, 0.f), fmaxf(acc[nt][3] + bb1, 0.f));
        }
    }
}

// ================= node update kernel (K=128 GEMM1, K=64 GEMM2) + fused norm stats ============
#define U_A    0
#define U_M    16896
#define U_B1H  25600
#define U_B1L  34304
#define U_B2H  43008
#define U_B2L  47616
#define U_BI1  52224
#define U_BI2  52288
#define U_FLOATS 52352
#define U_BYTES  (U_FLOATS * 4)

__global__ void __launch_bounds__(256) upd_mma_kernel(const float* __restrict__ w1,
                                                      const float* __restrict__ b1,
                                                      const float* __restrict__ w2,
                                                      const float* __restrict__ b2) {
    extern __shared__ float sm[];
    float* sA = sm + U_A;
    float* sM = sm + U_M;
    int tid = threadIdx.x;
    stage_Bt<128, 136>(sm + U_B1H, sm + U_B1L, w1);
    stage_Bt<64, 72>(sm + U_B2H, sm + U_B2L, w2);
    if (tid < 64) { sm[U_BI1 + tid] = b1[tid]; sm[U_BI2 + tid] = b2[tid]; }

    int warp = tid >> 5, lane = tid & 31, gid = lane >> 2, tig = lane & 3;
    int mr = (warp >> 1) * 32, n0 = (warp & 1) * 32;
    int nb0 = blockIdx.x * 128;

    #pragma unroll
    for (int it = 0; it < 16; it++) {
        int i = tid + it * 256;
        int e = i >> 5, part = i & 31;
        int node = nb0 + e;
        float4 v;
        if (part < 16) {
            v = *(const float4*)&g_h[node * 64 + part * 4];
        } else {
            float4* ap = (float4*)&g_agg[node * 64 + (part & 15) * 4];
            v = *ap;
            *ap = make_float4(0.f, 0.f, 0.f, 0.f);
        }
        *(float4*)&sA[e * 132 + part * 4] = v;
    }
    __syncthreads();
    float acc[2][4][4] = {};
    gemm_sp<128, 132, 4, 136>(sA, sm + U_B1H, sm + U_B1L, mr, n0, lane, acc);
    #pragma unroll
    for (int f = 0; f < 2; f++) {
        int r0 = mr + f * 16 + gid;
        #pragma unroll
        for (int nt = 0; nt < 4; nt++) {
            int col = n0 + nt * 8 + 2 * tig;
            float bb0 = sm[U_BI1 + col], bb1 = sm[U_BI1 + col + 1];
            sM[r0 * 68 + col]           = fmaxf(acc[f][nt][0] + bb0, 0.f);
            sM[r0 * 68 + col + 1]       = fmaxf(acc[f][nt][1] + bb1, 0.f);
            sM[(r0 + 8) * 68 + col]     = fmaxf(acc[f][nt][2] + bb0, 0.f);
            sM[(r0 + 8) * 68 + col + 1] = fmaxf(acc[f][nt][3] + bb1, 0.f);
        }
    }
    __syncthreads();
    float acc2[2][4][4] = {};
    gemm_sp<64, 68, 4, 72>(sM, sm + U_B2H, sm + U_B2L, mr, n0, lane, acc2);
    #pragma unroll
    for (int f = 0; f < 2; f++) {
        int r0 = mr + f * 16 + gid;
        #pragma unroll
        for (int nt = 0; nt < 4; nt++) {
            int col = n0 + nt * 8 + 2 * tig;
            float bb0 = sm[U_BI2 + col], bb1 = sm[U_BI2 + col + 1];
            sA[r0 * 68 + col]           = fmaxf(acc2[f][nt][0] + bb0, 0.f);
            sA[r0 * 68 + col + 1]       = fmaxf(acc2[f][nt][1] + bb1, 0.f);
            sA[(r0 + 8) * 68 + col]     = fmaxf(acc2[f][nt][2] + bb0, 0.f);
            sA[(r0 + 8) * 68 + col + 1] = fmaxf(acc2[f][nt][3] + bb1, 0.f);
        }
    }
    __syncthreads();
    // store + fused per-feature stats (tile is within one graph: 2048 % 128 == 0)
    int f4 = tid & 15;
    float4 s = make_float4(0.f, 0.f, 0.f, 0.f);
    float4 q = make_float4(0.f, 0.f, 0.f, 0.f);
    #pragma unroll
    for (int it = 0; it < 8; it++) {
        int idx = tid + it * 256;
        int row = idx >> 4;
        float4 v = *(const float4*)&sA[row * 68 + f4 * 4];
        *(float4*)&g_h[(nb0 + row) * 64 + f4 * 4] = v;
        s.x += v.x; s.y += v.y; s.z += v.z; s.w += v.w;
        q.x = fmaf(v.x, v.x, q.x); q.y = fmaf(v.y, v.y, q.y);
        q.z = fmaf(v.z, v.z, q.z); q.w = fmaf(v.w, v.w, q.w);
    }
    int g = nb0 >> 11;
    red_add_v4(&g_sum[g * 64 + f4 * 4], s);
    red_add_v4(&g_sqs[g * 64 + f4 * 4], q);
}

// ---------------- instance norm: standalone apply (final layer only) ----------------
__global__ void norm_apply_kernel() {
    int g = blockIdx.x >> 3, sl = blockIdx.x & 7;
    int tid = threadIdx.x;
    __shared__ float smean[64], srstd[64];
    if (tid < 64) {
        float mean = g_sum[g * 64 + tid] * (1.f / NSAMPLES);
        float var  = g_sqs[g * 64 + tid] * (1.f / NSAMPLES) - mean * mean;
        smean[tid] = mean;
        srstd[tid] = rsqrtf(var + EPSI);
    }
    __syncthreads();
    int f4 = tid & 15, rc = tid >> 4;
    int row0 = g * NSAMPLES + sl * 256 + rc * 16;
    float4 mn = *(const float4*)&smean[f4 * 4];
    float4 rs = *(const float4*)&srstd[f4 * 4];
    #pragma unroll
    for (int r = 0; r < 16; r++) {
        float4* p = (float4*)&g_h[(row0 + r) * 64 + f4 * 4];
        float4 v = *p;
        v.x = (v.x - mn.x) * rs.x; v.y = (v.y - mn.y) * rs.y;
        v.z = (v.z - mn.z) * rs.z; v.w = (v.w - mn.w) * rs.w;
        *p = v;
    }
}

// ---------------- decoder + t2 term ----------------
__global__ void dec_kernel(const float* __restrict__ w, const float* __restrict__ b) {
    int i = blockIdx.x * blockDim.x + threadIdx.x;
    const float* hr = &g_h[i * 64];
    float a0 = b[0], a1 = b[1], a2 = b[2], a3 = b[3];
    #pragma unroll 8
    for (int k = 0; k < 64; k++) {
        float hv = hr[k];
        a0 = fmaf(hv, w[k * 4 + 0], a0);
        a1 = fmaf(hv, w[k * 4 + 1], a1);
        a2 = fmaf(hv, w[k * 4 + 2], a2);
        a3 = fmaf(hv, w[k * 4 + 3], a3);
    }
    a0 = 1.f / (1.f + expf(-a0));
    a1 = 1.f / (1.f + expf(-a1));
    a2 = 1.f / (1.f + expf(-a2));
    a3 = 1.f / (1.f + expf(-a3));
    g_X[i * 4 + 0] = a0; g_X[i * 4 + 1] = a1;
    g_X[i * 4 + 2] = a2; g_X[i * 4 + 3] = a3;
    float pr = (1.f - a0 * a0) * (1.f - a1 * a1) * (1.f - a2 * a2) * (1.f - a3 * a3);
    #pragma unroll
    for (int off = 16; off > 0; off >>= 1)
        pr += __shfl_down_sync(0xffffffffu, pr, off);
    if ((threadIdx.x & 31) == 0) atomicAdd(&g_t2[i >> 11], pr);
}

// ---------------- t3 pairwise term ----------------
__global__ void t3_kernel() {
    int b = blockIdx.x;
    int g = b >> 6, ic = (b >> 2) & 15, jc = b & 3;
    int tid = threadIdx.x;         // 128
    __shared__ float4 sX[512];
    const float4* Xg = (const float4*)&g_X[(g * NSAMPLES) * 4];
    for (int j = tid; j < 512; j += 128) sX[j] = Xg[jc * 512 + j];
    __syncthreads();
    float4 xi = Xg[ic * 128 + tid];
    float acc = 0.f;
    #pragma unroll 4
    for (int j = 0; j < 512; j++) {
        float4 xj = sX[j];
        float p = (1.f - fmaxf(xi.x, xj.x)) * (1.f - fmaxf(xi.y, xj.y)) *
                  (1.f - fmaxf(xi.z, xj.z)) * (1.f - fmaxf(xi.w, xj.w));
        acc += p;
    }
    __shared__ float red[128];
    red[tid] = acc; __syncthreads();
    for (int off = 64; off > 0; off >>= 1) {
        if (tid < off) red[tid] += red[tid + off];
        __syncthreads();
    }
    if (tid == 0) atomicAdd(&g_t3[g], red[0]);
}

// ---------------- emit ----------------
__global__ void emit_kernel(float* __restrict__ out, int out_size) {
    int tid = blockIdx.x * blockDim.x + threadIdx.x;
    float loss = 0.f;
    if (tid == 0) {
        const float t1 = 1.0f / 81.0f;
        #pragma unroll
        for (int g = 0; g < NBATCH; g++) {
            float l = t1 - g_t2[g] * (2.0f / 32768.0f)
                         + g_t3[g] * (1.0f / (2048.f * 2048.f));
            loss += l;
        }
        loss *= (1.0f / NBATCH);
    }
    if (out_size == NN * DIMX) {
        if (tid < NN * DIMX) out[tid] = g_X[tid];
    } else {
        if (tid == 0) out[0] = loss;
        int idx = tid - 1;
        if (idx >= 0 && idx < NN * DIMX && (idx + 1) < out_size) out[1 + idx] = g_X[idx];
    }
}

// ---------------- launch ----------------
extern "C" void kernel_launch(void* const* d_in, const int* in_sizes, int n_in,
                              void* d_out, int out_size) {
    const float* x     = (const float*)d_in[0];
    const int*   eiraw = (const int*)  d_in[1];
    const float* enc_w = (const float*)d_in[2];
    const float* enc_b = (const float*)d_in[3];
    const float* m1_w  = (const float*)d_in[4];
    const float* m1_b  = (const float*)d_in[5];
    const float* m2_w  = (const float*)d_in[6];
    const float* m2_b  = (const float*)d_in[7];
    const float* u1_w  = (const float*)d_in[8];
    const float* u1_b  = (const float*)d_in[9];
    const float* u2_w  = (const float*)d_in[10];
    const float* u2_b  = (const float*)d_in[11];
    const float* dec_w = (const float*)d_in[12];
    const float* dec_b = (const float*)d_in[13];
    float* out = (float*)d_out;

    (void)cudaFuncSetAttribute(pq_kernel,       cudaFuncAttributeMaxDynamicSharedMemorySize, PQ_BYTES);
    (void)cudaFuncSetAttribute(edge_mma_kernel, cudaFuncAttributeMaxDynamicSharedMemorySize, E_BYTES);
    (void)cudaFuncSetAttribute(upd_mma_kernel,  cudaFuncAttributeMaxDynamicSharedMemorySize, U_BYTES);

    cvt_edges_kernel<<<(EE + 255) / 256, 256>>>(eiraw);
    enc_kernel<<<NN * NHID / 256, 256>>>(x, enc_w, enc_b);
    for (int l = 0; l < NLAYERS; l++) {
        // pq(l) also applies instance-norm of layer l-1 (stats from upd(l-1))
        pq_kernel<<<NN / 128, 256, PQ_BYTES>>>(m1_w + l * 128 * 64, m1_b + l * 64, l > 0);
        edge_mma_kernel<<<444, 256, E_BYTES>>>(m2_w + l * 64 * 64, m2_b + l * 64);
        upd_mma_kernel<<<NN / 128, 256, U_BYTES>>>(
            u1_w + l * 128 * 64, u1_b + l * 64, u2_w + l * 64 * 64, u2_b + l * 64);
    }
    norm_apply_kernel<<<64, 256>>>();   // final layer's norm (for decoder)
    dec_kernel<<<NN / 256, 256>>>(dec_w, dec_b);
    t3_kernel<<<512, 128>>>();
    emit_kernel<<<(NN * DIMX + 1 + 255) / 256, 256>>>(out, out_size);
}